// round 13
// baseline (speedup 1.0000x reference)
#include <cuda_runtime.h>
#include <math.h>

#define BB 4
#define NN 4096
#define DKK 64
#define MT 12                       // Fourier modes (truncation rel_err ~3e-6)
#define THALF 8.0
#define OMEGA1 0.39269908169872414f // pi/8
#define TILE 64
#define NBLK 256                    // BB*NN/TILE = grid size (all co-resident)
#define FSTR 132                    // per-mode row: [0:64) C, [64:128) S, cc, ss, pad2
#define FLEN (MT*FSTR)              // 1584

typedef unsigned long long ull;

struct CoefArg { float a[MT]; };

__device__ __align__(16) float g_Q[BB*NN];
__device__ __align__(16) float g_part[(size_t)NBLK*FLEN];   // x-features per tile
__device__ __align__(16) float g_feat[BB*FLEN];             // a_m-scaled V-features
__device__ unsigned g_bar1 = 0, g_bar2 = 0, g_bar3 = 0;

// ---- packed f32x2 helpers (Blackwell dual-lane FFMA, PTX-only) ----
__device__ __forceinline__ ull pk2(float lo, float hi) {
    ull r; asm("mov.b64 %0, {%1,%2};" : "=l"(r) : "f"(lo), "f"(hi)); return r;
}
__device__ __forceinline__ void upk2(ull v, float& lo, float& hi) {
    asm("mov.b64 {%0,%1}, %2;" : "=f"(lo), "=f"(hi) : "l"(v));
}
__device__ __forceinline__ ull fma2(ull a, ull b, ull c) {
    ull r; asm("fma.rn.f32x2 %0, %1, %2, %3;" : "=l"(r) : "l"(a), "l"(b), "l"(c)); return r;
}

// grid-wide barrier: all NBLK CTAs resident by construction (26KB smem, <128 regs)
__device__ __forceinline__ void grid_bar(unsigned* bar) {
    __syncthreads();
    if (threadIdx.x == 0) {
        __threadfence();
        atomicAdd(bar, 1u);
        while (atomicAdd(bar, 0u) < (unsigned)NBLK) __nanosleep(64);
        __threadfence();
    }
    __syncthreads();
}

// ---------------------------------------------------------------------------
// Single fused kernel: [P1] tile features -> bar -> [P2] reduce+GEMM (48 CTAs)
// -> bar -> [P3] per-token output+LN (4 tokens/thread). grid=256, block=256.
// ---------------------------------------------------------------------------
__global__ __launch_bounds__(256) void k_fused(
    const float* __restrict__ x, const float* __restrict__ Wv,
    const float* __restrict__ bv, const float* __restrict__ wq,
    const float* __restrict__ wk, const float* __restrict__ gamma,
    const float* __restrict__ beta, float* __restrict__ out, CoefArg ca)
{
    extern __shared__ float sm[];
    float* xs  = sm;                 // 64*68 = 4352
    float* cs2 = xs + TILE*68;       // 12*132 = 1584
    float* wqs = cs2 + MT*FSTR;      // 64
    float* wks = wqs + 64;           // 64
    // Phase-2 overlay (xs+cs2 dead after P1): Wvs 64*65, Xm 132, bvs 64
    float* Wvs = sm;
    float* Xm  = sm + 64*65;
    float* bvs = Xm + FSTR;

    const int t = threadIdx.x;
    const int blk = blockIdx.x;

    // ============ Phase 1: per-tile Q,K + Fourier features of x ============
    {
        const float* xt = x + (size_t)blk * TILE * DKK;
        const float4* xt4 = (const float4*)xt;
        #pragma unroll
        for (int it = 0; it < 4; it++) {
            int f = it*256 + t;
            float4 v = xt4[f];
            *(float4*)&xs[(f >> 4)*68 + (f & 15)*4] = v;
        }
        if (t < DKK) { wqs[t] = wq[t]; wks[t] = wk[t]; }
    }
    __syncthreads();

    {
        const int j = t >> 2, p = t & 3;
        float q = 0.f, k = 0.f;
        const float* xr = xs + j*68 + p*16;
        #pragma unroll
        for (int d = 0; d < 16; d++) {
            q = fmaf(xr[d], wqs[p*16 + d], q);
            k = fmaf(xr[d], wks[p*16 + d], k);
        }
        q += __shfl_xor_sync(0xffffffffu, q, 1);
        q += __shfl_xor_sync(0xffffffffu, q, 2);
        k += __shfl_xor_sync(0xffffffffu, k, 1);
        k += __shfl_xor_sync(0xffffffffu, k, 2);
        if (p == 0) g_Q[(size_t)blk*TILE + j] = q;
        float th = OMEGA1 * k;
        float s1, c1; __sincosf(th, &s1, &c1);
        float s0, c0; __sincosf(3.f * (float)p * th, &s0, &c0);
        #pragma unroll
        for (int mi = 0; mi < 3; mi++) {
            int m = 3*p + mi;
            *(float2*)&cs2[m*FSTR + 2*j] = make_float2(c0, s0);
            float cn = c0*c1 - s0*s1;
            s0 = fmaf(s0, c1, c0*s1);
            c0 = cn;
        }
    }
    __syncthreads();

    if (t < 16*MT) {
        const int d4 = t & 15, m = t >> 4;
        float aC0=0,aC1=0,aC2=0,aC3=0, aS0=0,aS1=0,aS2=0,aS3=0;
        float aCC=0.f, aSS=0.f;
        #pragma unroll 8
        for (int jt = 0; jt < TILE; jt++) {
            float4 v = *(const float4*)&xs[jt*68 + d4*4];
            float2 cp = *(const float2*)&cs2[m*FSTR + 2*jt];   // broadcast
            aC0 = fmaf(cp.x, v.x, aC0); aC1 = fmaf(cp.x, v.y, aC1);
            aC2 = fmaf(cp.x, v.z, aC2); aC3 = fmaf(cp.x, v.w, aC3);
            aS0 = fmaf(cp.y, v.x, aS0); aS1 = fmaf(cp.y, v.y, aS1);
            aS2 = fmaf(cp.y, v.z, aS2); aS3 = fmaf(cp.y, v.w, aS3);
            aCC += cp.x; aSS += cp.y;
        }
        float* bse = g_part + (size_t)blk * FLEN + m*FSTR;
        *(float4*)&bse[d4*4]      = make_float4(aC0, aC1, aC2, aC3);
        *(float4*)&bse[64 + d4*4] = make_float4(aS0, aS1, aS2, aS3);
        if (d4 == 0) { bse[128] = aCC; bse[129] = aSS; }
    }

    grid_bar(&g_bar1);

    // ============ Phase 2: reduce + Wv-GEMM + a_m folding (CTAs 0..47) ============
    if (blk < BB*MT) {
        const int b = blk / MT, m = blk % MT;
        const float am = ca.a[m];

        #pragma unroll
        for (int it = 0; it < 16; it++) {
            int i = it*256 + t;          // i = e*64 + d
            Wvs[(i >> 6)*65 + (i & 63)] = Wv[i];
        }
        if (t < DKK) bvs[t] = bv[t];
        if (t < FSTR) {
            const float* src = g_part + ((size_t)b*64)*FLEN + m*FSTR + t;
            float s = 0.f;
            #pragma unroll 16
            for (int tb = 0; tb < 64; tb++)
                s += src[(size_t)tb*FLEN];
            Xm[t] = s;
        }
        __syncthreads();

        const int h = t & 1, k2 = (t >> 1) & 1, e = t >> 2;
        const float* xv = Xm + k2*64 + h*32;
        const float* wr = Wvs + e*65 + h*32;
        float acc = 0.f;
        #pragma unroll
        for (int d = 0; d < 32; d++)
            acc = fmaf(xv[d], wr[d], acc);
        acc += __shfl_xor_sync(0xffffffffu, acc, 1);
        if (h == 0) {
            float sc = Xm[128 + k2];   // cc for C, ss for S
            g_feat[b*FLEN + m*FSTR + k2*64 + e] = am * fmaf(sc, bvs[e], acc);
        }
        if (t < 2)
            g_feat[b*FLEN + m*FSTR + 128 + t] = am * Xm[128 + t];
    }

    grid_bar(&g_bar2);

    // ============ Phase 3: per-token output + residual + LayerNorm ============
    // CTA owns 64 tokens; thread = (p = t&15 dim-slice, tg = t>>4): 4 tokens.
    {
        const int p = t & 15, tg = t >> 4;
        const int b = blk >> 6;              // 64 CTAs per batch
        const size_t tok0 = (size_t)blk*64 + tg*4;
        const float* gf = g_feat + b*FLEN;

        float cc0[4], ss0[4], cs[4], sn[4];
        ull nlo[4], nhi[4], dpk[4];
        #pragma unroll
        for (int i = 0; i < 4; i++) {
            float q = __ldg(&g_Q[tok0 + i]);
            __sincosf(OMEGA1*q, &ss0[i], &cc0[i]);
            cs[i] = 1.f; sn[i] = 0.f;
            nlo[i] = 0; nhi[i] = 0; dpk[i] = 0;
        }

        #pragma unroll
        for (int m = 0; m < MT; m++) {
            const float* bse = gf + m*FSTR;
            ull dd = __ldg((const ull*)(bse + 128));
            ulonglong2 C = __ldg((const ulonglong2*)(bse + p*4));
            ulonglong2 S = __ldg((const ulonglong2*)(bse + 64 + p*4));
            #pragma unroll
            for (int i = 0; i < 4; i++) {
                ull wc = pk2(cs[i], cs[i]), ws = pk2(sn[i], sn[i]);
                nlo[i] = fma2(wc, C.x, fma2(ws, S.x, nlo[i]));
                nhi[i] = fma2(wc, C.y, fma2(ws, S.y, nhi[i]));
                dpk[i] = fma2(pk2(cs[i], sn[i]), dd, dpk[i]);
                float cn = fmaf(cs[i], cc0[i], -(sn[i]*ss0[i]));
                sn[i] = fmaf(sn[i], cc0[i], cs[i]*ss0[i]);
                cs[i] = cn;
            }
        }

        float4 g4 = __ldg((const float4*)(gamma + p*4));
        float4 b4 = __ldg((const float4*)(beta  + p*4));

        #pragma unroll
        for (int i = 0; i < 4; i++) {
            size_t tok = tok0 + i;
            float dc, ds; upk2(dpk[i], dc, ds);
            float den = dc + ds;
            float4 num;
            upk2(nlo[i], num.x, num.y);
            upk2(nhi[i], num.z, num.w);

            float4 xr = *(const float4*)(x + tok*DKK + p*4);
            float invden = 1.f / den;
            num.x = fmaf(num.x, invden, xr.x);
            num.y = fmaf(num.y, invden, xr.y);
            num.z = fmaf(num.z, invden, xr.z);
            num.w = fmaf(num.w, invden, xr.w);

            float psum = num.x + num.y + num.z + num.w;
            psum += __shfl_xor_sync(0xffffffffu, psum, 1);
            psum += __shfl_xor_sync(0xffffffffu, psum, 2);
            psum += __shfl_xor_sync(0xffffffffu, psum, 4);
            psum += __shfl_xor_sync(0xffffffffu, psum, 8);
            float mu = psum * (1.f/64.f);

            float dx = num.x - mu, dy = num.y - mu, dz = num.z - mu, dw = num.w - mu;
            float pvar = dx*dx + dy*dy + dz*dz + dw*dw;
            pvar += __shfl_xor_sync(0xffffffffu, pvar, 1);
            pvar += __shfl_xor_sync(0xffffffffu, pvar, 2);
            pvar += __shfl_xor_sync(0xffffffffu, pvar, 4);
            pvar += __shfl_xor_sync(0xffffffffu, pvar, 8);
            float rstd = rsqrtf(pvar*(1.f/64.f) + 1e-5f);

            float4 o;
            o.x = dx * rstd * g4.x + b4.x;
            o.y = dy * rstd * g4.y + b4.y;
            o.z = dz * rstd * g4.z + b4.z;
            o.w = dw * rstd * g4.w + b4.w;
            *(float4*)(out + tok*DKK + p*4) = o;
        }
    }

    // ============ Epilogue: last CTA resets barriers for graph replay ============
    __syncthreads();
    if (t == 0) {
        unsigned old = atomicAdd(&g_bar3, 1u);
        if (old == (unsigned)(NBLK - 1)) {
            g_bar1 = 0; g_bar2 = 0; g_bar3 = 0;
            __threadfence();
        }
    }
}

// ---------------------------------------------------------------------------
extern "C" void kernel_launch(void* const* d_in, const int* in_sizes, int n_in,
                              void* d_out, int out_size)
{
    const float* x     = (const float*)d_in[0];
    const float* Wv    = (const float*)d_in[1];
    const float* bv    = (const float*)d_in[2];
    const float* wq    = (const float*)d_in[3];
    const float* wk    = (const float*)d_in[4];
    const float* gamma = (const float*)d_in[5];
    const float* beta  = (const float*)d_in[6];
    float* out = (float*)d_out;

    // Fourier cosine coefficients of g(t)=exp(exp(-t^2)/8), host double precision
    CoefArg ca;
    {
        const int P = 8192;
        const double T = THALF, L = 2.0*T;
        for (int m = 0; m < MT; m++) {
            double wm = 3.14159265358979323846 * (double)m / T;
            double sum = 0.0;
            for (int ip = 0; ip < P; ip++) {
                double tt = -T + (ip + 0.5) * (L / P);
                sum += exp(exp(-tt*tt) * 0.125) * cos(wm * tt);
            }
            ca.a[m] = (float)(((m == 0) ? 1.0 : 2.0) * sum / (double)P);
        }
    }

    const size_t sm1 = (size_t)(TILE*68 + MT*FSTR + 2*64) * sizeof(float);
    cudaFuncSetAttribute(k_fused, cudaFuncAttributeMaxDynamicSharedMemorySize, (int)sm1);

    k_fused<<<NBLK, 256, sm1>>>(x, Wv, bv, wq, wk, gamma, beta, out, ca);
}

// round 14
// speedup vs baseline: 1.0935x; 1.0935x over previous
#include <cuda_runtime.h>
#include <math.h>

#define BB 4
#define NN 4096
#define DKK 64
#define MT 12                       // Fourier modes (truncation rel_err ~3e-6)
#define THALF 8.0
#define OMEGA1 0.39269908169872414f // pi/8
#define TILE 64
#define NBLK 256                    // BB*NN/TILE
#define FSTR 132                    // per-mode row: [0:64) C, [64:128) S, cc, ss, pad2
#define FLEN (MT*FSTR)              // 1584

typedef unsigned long long ull;

struct CoefArg { float a[MT]; };

__device__ __align__(16) float g_Q[BB*NN];
__device__ __align__(16) float g_part[(size_t)NBLK*FLEN];   // x-features per tile
__device__ __align__(16) float g_feat[BB*FLEN];             // a_m-scaled V-features

// ---- packed f32x2 helpers (Blackwell dual-lane FFMA, PTX-only) ----
__device__ __forceinline__ ull pk2(float lo, float hi) {
    ull r; asm("mov.b64 %0, {%1,%2};" : "=l"(r) : "f"(lo), "f"(hi)); return r;
}
__device__ __forceinline__ void upk2(ull v, float& lo, float& hi) {
    asm("mov.b64 {%0,%1}, %2;" : "=f"(lo), "=f"(hi) : "l"(v));
}
__device__ __forceinline__ ull fma2(ull a, ull b, ull c) {
    ull r; asm("fma.rn.f32x2 %0, %1, %2, %3;" : "=l"(r) : "l"(a), "l"(b), "l"(c)); return r;
}

// ---------------------------------------------------------------------------
// K1: per-tile Q,K + Fourier features of x. grid=256, block=256, smem ~26KB.
// ---------------------------------------------------------------------------
__global__ __launch_bounds__(256) void k_main(
    const float* __restrict__ x, const float* __restrict__ wq,
    const float* __restrict__ wk)
{
    extern __shared__ float sm[];
    float* xs  = sm;                 // 64*68 = 4352
    float* cs2 = xs + TILE*68;       // 12*132 = 1584 (interleaved c,s per mode)
    float* wqs = cs2 + MT*FSTR;      // 64
    float* wks = wqs + 64;           // 64

    const int t = threadIdx.x;
    const int blk = blockIdx.x;
    const float* xt = x + (size_t)blk * TILE * DKK;

    // -- Phase A: stage x (float4, 4/thread) --
    {
        const float4* xt4 = (const float4*)xt;
        #pragma unroll
        for (int it = 0; it < 4; it++) {
            int f = it*256 + t;
            float4 v = xt4[f];
            *(float4*)&xs[(f >> 4)*68 + (f & 15)*4] = v;
        }
        if (t < DKK) { wqs[t] = wq[t]; wks[t] = wk[t]; }
    }
    __syncthreads();

    const int j = t >> 2, p = t & 3;

    // -- Phase B: Q,K scalars (quad-split) + mode table (4 lanes x 3 modes) --
    {
        float q = 0.f, k = 0.f;
        const float* xr = xs + j*68 + p*16;
        #pragma unroll
        for (int d = 0; d < 16; d++) {
            q = fmaf(xr[d], wqs[p*16 + d], q);
            k = fmaf(xr[d], wks[p*16 + d], k);
        }
        q += __shfl_xor_sync(0xffffffffu, q, 1);
        q += __shfl_xor_sync(0xffffffffu, q, 2);
        k += __shfl_xor_sync(0xffffffffu, k, 1);
        k += __shfl_xor_sync(0xffffffffu, k, 2);
        if (p == 0) g_Q[(size_t)blk*TILE + j] = q;
        float th = OMEGA1 * k;
        float s1, c1; __sincosf(th, &s1, &c1);
        float s0, c0; __sincosf(3.f * (float)p * th, &s0, &c0);
        #pragma unroll
        for (int mi = 0; mi < 3; mi++) {
            int m = 3*p + mi;
            *(float2*)&cs2[m*FSTR + 2*j] = make_float2(c0, s0);
            float cn = c0*c1 - s0*s1;
            s0 = fmaf(s0, c1, c0*s1);
            c0 = cn;
        }
    }
    __syncthreads();

    // -- Phase D: x-feature rank update. t<192: (d4 = t&15, m = t>>4) --
    if (t < 16*MT) {
        const int d4 = t & 15, m = t >> 4;
        float aC0=0,aC1=0,aC2=0,aC3=0, aS0=0,aS1=0,aS2=0,aS3=0;
        float aCC=0.f, aSS=0.f;
        #pragma unroll 8
        for (int jt = 0; jt < TILE; jt++) {
            float4 v = *(const float4*)&xs[jt*68 + d4*4];
            float2 cp = *(const float2*)&cs2[m*FSTR + 2*jt];   // broadcast
            aC0 = fmaf(cp.x, v.x, aC0); aC1 = fmaf(cp.x, v.y, aC1);
            aC2 = fmaf(cp.x, v.z, aC2); aC3 = fmaf(cp.x, v.w, aC3);
            aS0 = fmaf(cp.y, v.x, aS0); aS1 = fmaf(cp.y, v.y, aS1);
            aS2 = fmaf(cp.y, v.z, aS2); aS3 = fmaf(cp.y, v.w, aS3);
            aCC += cp.x; aSS += cp.y;
        }
        float* bse = g_part + (size_t)blk * FLEN + m*FSTR;
        *(float4*)&bse[d4*4]      = make_float4(aC0, aC1, aC2, aC3);
        *(float4*)&bse[64 + d4*4] = make_float4(aS0, aS1, aS2, aS3);
        if (d4 == 0) { bse[128] = aCC; bse[129] = aSS; }
    }
}

// ---------------------------------------------------------------------------
// K2: fused reduce + Wv-GEMM + a_m folding.
// grid=(BB, MT) = 48 CTAs, block=256. Each CTA owns one (batch, mode) row.
// ---------------------------------------------------------------------------
__global__ __launch_bounds__(256) void k_rg(
    const float* __restrict__ Wv, const float* __restrict__ bv, CoefArg ca)
{
    extern __shared__ float sm[];
    float* Wvs = sm;                 // 64*65 = 4160 (padded rows)
    float* Xm  = Wvs + 64*65;        // 132
    float* bvs = Xm + FSTR;          // 64

    const int t = threadIdx.x;
    const int b = blockIdx.x;
    const int m = blockIdx.y;
    const float am = ca.a[m];

    #pragma unroll
    for (int it = 0; it < 16; it++) {
        int i = it*256 + t;          // i = e*64 + d
        Wvs[(i >> 6)*65 + (i & 63)] = Wv[i];
    }
    if (t < DKK) bvs[t] = bv[t];

    if (t < FSTR) {
        const float* src = g_part + ((size_t)b*64)*FLEN + m*FSTR + t;
        float s = 0.f;
        #pragma unroll 16
        for (int tb = 0; tb < 64; tb++)
            s += src[(size_t)tb*FLEN];
        Xm[t] = s;
    }
    __syncthreads();

    const int h = t & 1, k2 = (t >> 1) & 1, e = t >> 2;
    {
        const float* xv = Xm + k2*64 + h*32;
        const float* wr = Wvs + e*65 + h*32;
        float acc = 0.f;
        #pragma unroll
        for (int d = 0; d < 32; d++)
            acc = fmaf(xv[d], wr[d], acc);
        acc += __shfl_xor_sync(0xffffffffu, acc, 1);
        if (h == 0) {
            float sc = Xm[128 + k2];   // cc for C, ss for S
            g_feat[b*FLEN + m*FSTR + k2*64 + e] = am * fmaf(sc, bvs[e], acc);
        }
        if (t < 2)
            g_feat[b*FLEN + m*FSTR + 128 + t] = am * Xm[128 + t];
    }
}

// ---------------------------------------------------------------------------
// K3: per-token output + residual + LayerNorm.
// grid=256, block=256. Thread = (p = t&15 dim-slice, tg = t>>4): 4 tokens.
// C/S/dd loads shared across all 4 tokens (2x fewer LDG than 2-token layout).
// ---------------------------------------------------------------------------
__global__ __launch_bounds__(256) void k_out(
    const float* __restrict__ x, const float* __restrict__ gamma,
    const float* __restrict__ beta, float* __restrict__ out)
{
    const int t = threadIdx.x;
    const int blk = blockIdx.x;          // 256 blocks, 64 tokens each
    const int b = blk >> 6;              // 64 blocks per batch

    const int p = t & 15, tg = t >> 4;
    const size_t tok0 = (size_t)blk*64 + tg*4;
    const float* gf = g_feat + b*FLEN;

    float cc0[4], ss0[4], cs[4], sn[4];
    ull nlo[4], nhi[4], dpk[4];
    #pragma unroll
    for (int i = 0; i < 4; i++) {
        float q = __ldg(&g_Q[tok0 + i]);
        __sincosf(OMEGA1*q, &ss0[i], &cc0[i]);
        cs[i] = 1.f; sn[i] = 0.f;
        nlo[i] = 0; nhi[i] = 0; dpk[i] = 0;
    }

    #pragma unroll
    for (int m = 0; m < MT; m++) {
        const float* bse = gf + m*FSTR;
        ull dd = __ldg((const ull*)(bse + 128));
        ulonglong2 C = __ldg((const ulonglong2*)(bse + p*4));
        ulonglong2 S = __ldg((const ulonglong2*)(bse + 64 + p*4));
        #pragma unroll
        for (int i = 0; i < 4; i++) {
            ull wc = pk2(cs[i], cs[i]), ws = pk2(sn[i], sn[i]);
            nlo[i] = fma2(wc, C.x, fma2(ws, S.x, nlo[i]));
            nhi[i] = fma2(wc, C.y, fma2(ws, S.y, nhi[i]));
            dpk[i] = fma2(pk2(cs[i], sn[i]), dd, dpk[i]);
            float cn = fmaf(cs[i], cc0[i], -(sn[i]*ss0[i]));
            sn[i] = fmaf(sn[i], cc0[i], cs[i]*ss0[i]);
            cs[i] = cn;
        }
    }

    float4 g4 = __ldg((const float4*)(gamma + p*4));
    float4 b4 = __ldg((const float4*)(beta  + p*4));

    #pragma unroll
    for (int i = 0; i < 4; i++) {
        size_t tok = tok0 + i;
        float dc, ds; upk2(dpk[i], dc, ds);
        float den = dc + ds;
        float4 num;
        upk2(nlo[i], num.x, num.y);
        upk2(nhi[i], num.z, num.w);

        float4 xr = *(const float4*)(x + tok*DKK + p*4);
        float invden = 1.f / den;
        num.x = fmaf(num.x, invden, xr.x);
        num.y = fmaf(num.y, invden, xr.y);
        num.z = fmaf(num.z, invden, xr.z);
        num.w = fmaf(num.w, invden, xr.w);

        float psum = num.x + num.y + num.z + num.w;
        psum += __shfl_xor_sync(0xffffffffu, psum, 1);
        psum += __shfl_xor_sync(0xffffffffu, psum, 2);
        psum += __shfl_xor_sync(0xffffffffu, psum, 4);
        psum += __shfl_xor_sync(0xffffffffu, psum, 8);
        float mu = psum * (1.f/64.f);

        float dx = num.x - mu, dy = num.y - mu, dz = num.z - mu, dw = num.w - mu;
        float pvar = dx*dx + dy*dy + dz*dz + dw*dw;
        pvar += __shfl_xor_sync(0xffffffffu, pvar, 1);
        pvar += __shfl_xor_sync(0xffffffffu, pvar, 2);
        pvar += __shfl_xor_sync(0xffffffffu, pvar, 4);
        pvar += __shfl_xor_sync(0xffffffffu, pvar, 8);
        float rstd = rsqrtf(pvar*(1.f/64.f) + 1e-5f);

        float4 o;
        o.x = dx * rstd * g4.x + b4.x;
        o.y = dy * rstd * g4.y + b4.y;
        o.z = dz * rstd * g4.z + b4.z;
        o.w = dw * rstd * g4.w + b4.w;
        *(float4*)(out + tok*DKK + p*4) = o;
    }
}

// ---------------------------------------------------------------------------
extern "C" void kernel_launch(void* const* d_in, const int* in_sizes, int n_in,
                              void* d_out, int out_size)
{
    const float* x     = (const float*)d_in[0];
    const float* Wv    = (const float*)d_in[1];
    const float* bv    = (const float*)d_in[2];
    const float* wq    = (const float*)d_in[3];
    const float* wk    = (const float*)d_in[4];
    const float* gamma = (const float*)d_in[5];
    const float* beta  = (const float*)d_in[6];
    float* out = (float*)d_out;

    // Fourier cosine coefficients of g(t)=exp(exp(-t^2)/8), host double precision
    CoefArg ca;
    {
        const int P = 8192;
        const double T = THALF, L = 2.0*T;
        for (int m = 0; m < MT; m++) {
            double wm = 3.14159265358979323846 * (double)m / T;
            double sum = 0.0;
            for (int ip = 0; ip < P; ip++) {
                double tt = -T + (ip + 0.5) * (L / P);
                sum += exp(exp(-tt*tt) * 0.125) * cos(wm * tt);
            }
            ca.a[m] = (float)(((m == 0) ? 1.0 : 2.0) * sum / (double)P);
        }
    }

    const size_t sm1 = (size_t)(TILE*68 + MT*FSTR + 2*64) * sizeof(float);
    const size_t smg = (size_t)(64*65 + FSTR + 64) * sizeof(float);
    cudaFuncSetAttribute(k_main, cudaFuncAttributeMaxDynamicSharedMemorySize, (int)sm1);
    cudaFuncSetAttribute(k_rg,   cudaFuncAttributeMaxDynamicSharedMemorySize, (int)smg);

    k_main<<<NBLK, 256, sm1>>>(x, wq, wk);
    k_rg<<<dim3(BB, MT), 256, smg>>>(Wv, bv, ca);
    k_out<<<256, 256>>>(x, gamma, beta, out);
}

// round 15
// speedup vs baseline: 1.2429x; 1.1366x over previous
#include <cuda_runtime.h>
#include <math.h>

#define BB 4
#define NN 4096
#define DKK 64
#define MT 12                       // Fourier modes (truncation rel_err ~3e-6)
#define THALF 8.0
#define OMEGA1 0.39269908169872414f // pi/8
#define TILE 64
#define NBLK 256                    // BB*NN/TILE
#define FSTR 132                    // per-mode row: [0:64) C, [64:128) S, cc, ss, pad2
#define FLEN (MT*FSTR)              // 1584

typedef unsigned long long ull;

struct CoefArg { float a[MT]; };

__device__ __align__(16) float g_Q[BB*NN];
__device__ __align__(16) float g_part[(size_t)NBLK*FLEN];   // x-features per tile
__device__ __align__(16) float g_feat[BB*FLEN];             // a_m-scaled V-features

// ---- packed f32x2 helpers (Blackwell dual-lane FFMA, PTX-only) ----
__device__ __forceinline__ ull pk2(float lo, float hi) {
    ull r; asm("mov.b64 %0, {%1,%2};" : "=l"(r) : "f"(lo), "f"(hi)); return r;
}
__device__ __forceinline__ void upk2(ull v, float& lo, float& hi) {
    asm("mov.b64 {%0,%1}, %2;" : "=f"(lo), "=f"(hi) : "l"(v));
}
__device__ __forceinline__ ull fma2(ull a, ull b, ull c) {
    ull r; asm("fma.rn.f32x2 %0, %1, %2, %3;" : "=l"(r) : "l"(a), "l"(b), "l"(c)); return r;
}

// ---- PDL primitives ----
__device__ __forceinline__ void pdl_trigger() {
    asm volatile("griddepcontrol.launch_dependents;");
}
__device__ __forceinline__ void pdl_wait() {
    asm volatile("griddepcontrol.wait;" ::: "memory");
}

// ---------------------------------------------------------------------------
// K1: per-tile Q,K + Fourier features of x. grid=256, block=256, smem ~26KB.
// ---------------------------------------------------------------------------
__global__ __launch_bounds__(256) void k_main(
    const float* __restrict__ x, const float* __restrict__ wq,
    const float* __restrict__ wk)
{
    extern __shared__ float sm[];
    float* xs  = sm;                 // 64*68 = 4352
    float* cs2 = xs + TILE*68;       // 12*132 = 1584 (interleaved c,s per mode)
    float* wqs = cs2 + MT*FSTR;      // 64
    float* wks = wqs + 64;           // 64

    const int t = threadIdx.x;
    const int blk = blockIdx.x;

    pdl_trigger();   // dependents may start their independent prologues

    const float* xt = x + (size_t)blk * TILE * DKK;

    // -- Phase A: stage x (float4, 4/thread) --
    {
        const float4* xt4 = (const float4*)xt;
        #pragma unroll
        for (int it = 0; it < 4; it++) {
            int f = it*256 + t;
            float4 v = xt4[f];
            *(float4*)&xs[(f >> 4)*68 + (f & 15)*4] = v;
        }
        if (t < DKK) { wqs[t] = wq[t]; wks[t] = wk[t]; }
    }
    __syncthreads();

    const int j = t >> 2, p = t & 3;

    // -- Phase B: Q,K scalars (quad-split) + mode table (4 lanes x 3 modes) --
    {
        float q = 0.f, k = 0.f;
        const float* xr = xs + j*68 + p*16;
        #pragma unroll
        for (int d = 0; d < 16; d++) {
            q = fmaf(xr[d], wqs[p*16 + d], q);
            k = fmaf(xr[d], wks[p*16 + d], k);
        }
        q += __shfl_xor_sync(0xffffffffu, q, 1);
        q += __shfl_xor_sync(0xffffffffu, q, 2);
        k += __shfl_xor_sync(0xffffffffu, k, 1);
        k += __shfl_xor_sync(0xffffffffu, k, 2);
        if (p == 0) g_Q[(size_t)blk*TILE + j] = q;
        float th = OMEGA1 * k;
        float s1, c1; __sincosf(th, &s1, &c1);
        float s0, c0; __sincosf(3.f * (float)p * th, &s0, &c0);
        #pragma unroll
        for (int mi = 0; mi < 3; mi++) {
            int m = 3*p + mi;
            *(float2*)&cs2[m*FSTR + 2*j] = make_float2(c0, s0);
            float cn = c0*c1 - s0*s1;
            s0 = fmaf(s0, c1, c0*s1);
            c0 = cn;
        }
    }
    __syncthreads();

    // -- Phase D: x-feature rank update. t<192: (d4 = t&15, m = t>>4) --
    if (t < 16*MT) {
        const int d4 = t & 15, m = t >> 4;
        float aC0=0,aC1=0,aC2=0,aC3=0, aS0=0,aS1=0,aS2=0,aS3=0;
        float aCC=0.f, aSS=0.f;
        #pragma unroll 8
        for (int jt = 0; jt < TILE; jt++) {
            float4 v = *(const float4*)&xs[jt*68 + d4*4];
            float2 cp = *(const float2*)&cs2[m*FSTR + 2*jt];   // broadcast
            aC0 = fmaf(cp.x, v.x, aC0); aC1 = fmaf(cp.x, v.y, aC1);
            aC2 = fmaf(cp.x, v.z, aC2); aC3 = fmaf(cp.x, v.w, aC3);
            aS0 = fmaf(cp.y, v.x, aS0); aS1 = fmaf(cp.y, v.y, aS1);
            aS2 = fmaf(cp.y, v.z, aS2); aS3 = fmaf(cp.y, v.w, aS3);
            aCC += cp.x; aSS += cp.y;
        }
        float* bse = g_part + (size_t)blk * FLEN + m*FSTR;
        *(float4*)&bse[d4*4]      = make_float4(aC0, aC1, aC2, aC3);
        *(float4*)&bse[64 + d4*4] = make_float4(aS0, aS1, aS2, aS3);
        if (d4 == 0) { bse[128] = aCC; bse[129] = aSS; }
    }
}

// ---------------------------------------------------------------------------
// K2: fused reduce + Wv-GEMM + a_m folding. grid=(BB, MT) = 48 CTAs.
// PDL: stages Wv/bv BEFORE waiting on k_main.
// ---------------------------------------------------------------------------
__global__ __launch_bounds__(256) void k_rg(
    const float* __restrict__ Wv, const float* __restrict__ bv, CoefArg ca)
{
    extern __shared__ float sm[];
    float* Wvs = sm;                 // 64*65 = 4160 (padded rows)
    float* Xm  = Wvs + 64*65;        // 132
    float* bvs = Xm + FSTR;          // 64

    const int t = threadIdx.x;
    const int b = blockIdx.x;
    const int m = blockIdx.y;
    const float am = ca.a[m];

    pdl_trigger();   // k_out may start its independent prologue

    // stage Wv + bv (independent of k_main's outputs)
    #pragma unroll
    for (int it = 0; it < 16; it++) {
        int i = it*256 + t;          // i = e*64 + d
        Wvs[(i >> 6)*65 + (i & 63)] = Wv[i];
    }
    if (t < DKK) bvs[t] = bv[t];

    pdl_wait();      // k_main outputs (g_part) now visible

    if (t < FSTR) {
        const float* src = g_part + ((size_t)b*64)*FLEN + m*FSTR + t;
        float s = 0.f;
        #pragma unroll 16
        for (int tb = 0; tb < 64; tb++)
            s += src[(size_t)tb*FLEN];
        Xm[t] = s;
    }
    __syncthreads();

    const int h = t & 1, k2 = (t >> 1) & 1, e = t >> 2;
    {
        const float* xv = Xm + k2*64 + h*32;
        const float* wr = Wvs + e*65 + h*32;
        float acc = 0.f;
        #pragma unroll
        for (int d = 0; d < 32; d++)
            acc = fmaf(xv[d], wr[d], acc);
        acc += __shfl_xor_sync(0xffffffffu, acc, 1);
        if (h == 0) {
            float sc = Xm[128 + k2];   // cc for C, ss for S
            g_feat[b*FLEN + m*FSTR + k2*64 + e] = am * fmaf(sc, bvs[e], acc);
        }
        if (t < 2)
            g_feat[b*FLEN + m*FSTR + 128 + t] = am * Xm[128 + t];
    }
}

// ---------------------------------------------------------------------------
// K3: per-token output + residual + LayerNorm.
// grid=256, block=256. Thread = (p = t&15, tg = t>>4): 4 tokens.
// PDL: loads x/gamma/beta BEFORE waiting (they are harness inputs, not
// k_main/k_rg outputs); g_Q + g_feat consumed only after the wait, which
// transitively orders after k_main too (k_rg completion implies it).
// ---------------------------------------------------------------------------
__global__ __launch_bounds__(256) void k_out(
    const float* __restrict__ x, const float* __restrict__ gamma,
    const float* __restrict__ beta, float* __restrict__ out)
{
    const int t = threadIdx.x;
    const int blk = blockIdx.x;          // 256 blocks, 64 tokens each
    const int b = blk >> 6;              // 64 blocks per batch

    const int p = t & 15, tg = t >> 4;
    const size_t tok0 = (size_t)blk*64 + tg*4;
    const float* gf = g_feat + b*FLEN;

    // independent prologue: residual x rows, gamma, beta
    float4 xr4[4];
    #pragma unroll
    for (int i = 0; i < 4; i++)
        xr4[i] = *(const float4*)(x + (tok0 + i)*DKK + p*4);
    float4 g4 = __ldg((const float4*)(gamma + p*4));
    float4 b4 = __ldg((const float4*)(beta  + p*4));

    pdl_wait();      // g_Q / g_feat now valid

    float cc0[4], ss0[4], cs[4], sn[4];
    ull nlo[4], nhi[4], dpk[4];
    #pragma unroll
    for (int i = 0; i < 4; i++) {
        float q = __ldg(&g_Q[tok0 + i]);
        __sincosf(OMEGA1*q, &ss0[i], &cc0[i]);
        cs[i] = 1.f; sn[i] = 0.f;
        nlo[i] = 0; nhi[i] = 0; dpk[i] = 0;
    }

    #pragma unroll
    for (int m = 0; m < MT; m++) {
        const float* bse = gf + m*FSTR;
        ull dd = __ldg((const ull*)(bse + 128));
        ulonglong2 C = __ldg((const ulonglong2*)(bse + p*4));
        ulonglong2 S = __ldg((const ulonglong2*)(bse + 64 + p*4));
        #pragma unroll
        for (int i = 0; i < 4; i++) {
            ull wc = pk2(cs[i], cs[i]), ws = pk2(sn[i], sn[i]);
            nlo[i] = fma2(wc, C.x, fma2(ws, S.x, nlo[i]));
            nhi[i] = fma2(wc, C.y, fma2(ws, S.y, nhi[i]));
            dpk[i] = fma2(pk2(cs[i], sn[i]), dd, dpk[i]);
            float cn = fmaf(cs[i], cc0[i], -(sn[i]*ss0[i]));
            sn[i] = fmaf(sn[i], cc0[i], cs[i]*ss0[i]);
            cs[i] = cn;
        }
    }

    #pragma unroll
    for (int i = 0; i < 4; i++) {
        size_t tok = tok0 + i;
        float dc, ds; upk2(dpk[i], dc, ds);
        float den = dc + ds;
        float4 num;
        upk2(nlo[i], num.x, num.y);
        upk2(nhi[i], num.z, num.w);

        float invden = 1.f / den;
        num.x = fmaf(num.x, invden, xr4[i].x);
        num.y = fmaf(num.y, invden, xr4[i].y);
        num.z = fmaf(num.z, invden, xr4[i].z);
        num.w = fmaf(num.w, invden, xr4[i].w);

        float psum = num.x + num.y + num.z + num.w;
        psum += __shfl_xor_sync(0xffffffffu, psum, 1);
        psum += __shfl_xor_sync(0xffffffffu, psum, 2);
        psum += __shfl_xor_sync(0xffffffffu, psum, 4);
        psum += __shfl_xor_sync(0xffffffffu, psum, 8);
        float mu = psum * (1.f/64.f);

        float dx = num.x - mu, dy = num.y - mu, dz = num.z - mu, dw = num.w - mu;
        float pvar = dx*dx + dy*dy + dz*dz + dw*dw;
        pvar += __shfl_xor_sync(0xffffffffu, pvar, 1);
        pvar += __shfl_xor_sync(0xffffffffu, pvar, 2);
        pvar += __shfl_xor_sync(0xffffffffu, pvar, 4);
        pvar += __shfl_xor_sync(0xffffffffu, pvar, 8);
        float rstd = rsqrtf(pvar*(1.f/64.f) + 1e-5f);

        float4 o;
        o.x = dx * rstd * g4.x + b4.x;
        o.y = dy * rstd * g4.y + b4.y;
        o.z = dz * rstd * g4.z + b4.z;
        o.w = dw * rstd * g4.w + b4.w;
        *(float4*)(out + tok*DKK + p*4) = o;
    }
}

// ---------------------------------------------------------------------------
extern "C" void kernel_launch(void* const* d_in, const int* in_sizes, int n_in,
                              void* d_out, int out_size)
{
    const float* x     = (const float*)d_in[0];
    const float* Wv    = (const float*)d_in[1];
    const float* bv    = (const float*)d_in[2];
    const float* wq    = (const float*)d_in[3];
    const float* wk    = (const float*)d_in[4];
    const float* gamma = (const float*)d_in[5];
    const float* beta  = (const float*)d_in[6];
    float* out = (float*)d_out;

    // Fourier cosine coefficients of g(t)=exp(exp(-t^2)/8), host double precision
    CoefArg ca;
    {
        const int P = 8192;
        const double T = THALF, L = 2.0*T;
        for (int m = 0; m < MT; m++) {
            double wm = 3.14159265358979323846 * (double)m / T;
            double sum = 0.0;
            for (int ip = 0; ip < P; ip++) {
                double tt = -T + (ip + 0.5) * (L / P);
                sum += exp(exp(-tt*tt) * 0.125) * cos(wm * tt);
            }
            ca.a[m] = (float)(((m == 0) ? 1.0 : 2.0) * sum / (double)P);
        }
    }

    const size_t sm1 = (size_t)(TILE*68 + MT*FSTR + 2*64) * sizeof(float);
    const size_t smg = (size_t)(64*65 + FSTR + 64) * sizeof(float);
    cudaFuncSetAttribute(k_main, cudaFuncAttributeMaxDynamicSharedMemorySize, (int)sm1);
    cudaFuncSetAttribute(k_rg,   cudaFuncAttributeMaxDynamicSharedMemorySize, (int)smg);

    // k_main: plain launch (chain head)
    k_main<<<NBLK, 256, sm1>>>(x, wq, wk);

    // k_rg, k_out: PDL-serialized launches (overlap with predecessor tail)
    cudaLaunchAttribute at[1];
    at[0].id = cudaLaunchAttributeProgrammaticStreamSerialization;
    at[0].val.programmaticStreamSerializationAllowed = 1;

    {
        cudaLaunchConfig_t cfg = {};
        cfg.gridDim = dim3(BB, MT);
        cfg.blockDim = dim3(256);
        cfg.dynamicSmemBytes = smg;
        cfg.stream = 0;
        cfg.attrs = at;
        cfg.numAttrs = 1;
        cudaLaunchKernelEx(&cfg, k_rg, Wv, bv, ca);
    }
    {
        cudaLaunchConfig_t cfg = {};
        cfg.gridDim = dim3(256);
        cfg.blockDim = dim3(256);
        cfg.dynamicSmemBytes = 0;
        cfg.stream = 0;
        cfg.attrs = at;
        cfg.numAttrs = 1;
        cudaLaunchKernelEx(&cfg, k_out, x, gamma, beta, out);
    }
}